// round 8
// baseline (speedup 1.0000x reference)
#include <cuda_runtime.h>

#define NUM_B  4
#define SEQ    2048
#define DMODEL 1024
#define NH     16
#define DHEAD  64
#define MTOT   (NUM_B * SEQ)   // 8192

// Scratch (allocation-free rule: __device__ globals)
__device__ float g_q[(size_t)NUM_B * NH * SEQ * DHEAD];     // [B,H,S,Dh]
__device__ float g_k[(size_t)NUM_B * NH * SEQ * DHEAD];
__device__ float g_v[(size_t)NUM_B * NH * SEQ * DHEAD];
__device__ float g_attn[(size_t)NUM_B * SEQ * DMODEL];      // [B,S,D]

// ---------------------------------------------------------------------------
// Core 128x128x8 fp32 GEMM mainloop. 256 threads, 8x8 microtile per thread.
// C_tile = A[rowBase:+128, :K] * B[:K, colBase:+128]   (both row-major)
// ---------------------------------------------------------------------------
__device__ __forceinline__ void gemm_mainloop(
    const float* __restrict__ Ablk,   // A + rowBase*K
    const float* __restrict__ Bblk,   // B + colBase
    int K, int N,
    float (&acc)[8][8],
    float (*As)[128], float (*Bs)[128])
{
    const int t    = threadIdx.x;
    const int aRow = t >> 1, aCol = (t & 1) * 4;
    const int bRow = t >> 5, bCol = (t & 31) * 4;
    const int tRow = t >> 4, tCol = t & 15;

    for (int k0 = 0; k0 < K; k0 += 8) {
        float4 av = *(const float4*)(Ablk + (size_t)aRow * K + k0 + aCol);
        As[aCol + 0][aRow] = av.x;
        As[aCol + 1][aRow] = av.y;
        As[aCol + 2][aRow] = av.z;
        As[aCol + 3][aRow] = av.w;
        *(float4*)(&Bs[bRow][bCol]) =
            *(const float4*)(Bblk + (size_t)(k0 + bRow) * N + bCol);
        __syncthreads();
#pragma unroll
        for (int k = 0; k < 8; k++) {
            float ra[8], rb[8];
            *(float4*)&ra[0] = *(const float4*)&As[k][tRow * 8];
            *(float4*)&ra[4] = *(const float4*)&As[k][tRow * 8 + 4];
            *(float4*)&rb[0] = *(const float4*)&Bs[k][tCol * 8];
            *(float4*)&rb[4] = *(const float4*)&Bs[k][tCol * 8 + 4];
#pragma unroll
            for (int i = 0; i < 8; i++)
#pragma unroll
                for (int j = 0; j < 8; j++)
                    acc[i][j] += ra[i] * rb[j];
        }
        __syncthreads();
    }
}

// ---------------------------------------------------------------------------
// Kernel 1: fused QKV projection. grid = (N/128, M/128, 3), block = 256.
// Output scattered into [B,H,S,Dh] scratch layout.
// ---------------------------------------------------------------------------
__global__ __launch_bounds__(256)
void qkv_proj_kernel(const float* __restrict__ xq, const float* __restrict__ xk,
                     const float* __restrict__ xv,
                     const float* __restrict__ Wq, const float* __restrict__ Wk,
                     const float* __restrict__ Wv,
                     const float* __restrict__ bq, const float* __restrict__ bk,
                     const float* __restrict__ bv)
{
    __shared__ float As[8][128];
    __shared__ float Bs[8][128];

    const int sel = blockIdx.z;
    const float* X    = (sel == 0) ? xq : (sel == 1) ? xk : xv;
    const float* W    = (sel == 0) ? Wq : (sel == 1) ? Wk : Wv;
    const float* bias = (sel == 0) ? bq : (sel == 1) ? bk : bv;
    float* dst        = (sel == 0) ? g_q : (sel == 1) ? g_k : g_v;

    const int rowBase = blockIdx.y * 128;
    const int colBase = blockIdx.x * 128;

    float acc[8][8];
#pragma unroll
    for (int i = 0; i < 8; i++)
#pragma unroll
        for (int j = 0; j < 8; j++) acc[i][j] = 0.f;

    gemm_mainloop(X + (size_t)rowBase * DMODEL, W + colBase, DMODEL, DMODEL,
                  acc, As, Bs);

    const int t = threadIdx.x;
    const int tRow = t >> 4, tCol = t & 15;
#pragma unroll
    for (int i = 0; i < 8; i++) {
        const int r = rowBase + tRow * 8 + i;     // r = b*SEQ + s
        const int b = r / SEQ, s = r % SEQ;
#pragma unroll
        for (int j4 = 0; j4 < 8; j4 += 4) {
            const int n = colBase + tCol * 8 + j4; // n = h*DHEAD + d (j4 block stays in one head)
            const int h = n / DHEAD, d = n % DHEAD;
            float4 o;
            o.x = acc[i][j4 + 0] + bias[n + 0];
            o.y = acc[i][j4 + 1] + bias[n + 1];
            o.z = acc[i][j4 + 2] + bias[n + 2];
            o.w = acc[i][j4 + 3] + bias[n + 3];
            *(float4*)(dst + (((size_t)(b * NH + h) * SEQ + s) * DHEAD + d)) = o;
        }
    }
}

// ---------------------------------------------------------------------------
// Kernel 2: flash attention. grid = (SEQ/128, B*H), block = 256, dyn smem.
// Per block: 128 q-rows of one (b,h). Iterates 64-key tiles with online softmax.
// Microtile per thread: 8 q-rows (tRow) x 4 cols (tCol). Row stats reduced via
// 16-lane shfl (row groups are contiguous half-warps).
// ---------------------------------------------------------------------------
#define ATTN_SMEM_FLOATS (128*64 + 64*65 + 64*64 + 128*64)   // Qs, Kts(+pad), Vs, Ps

__global__ __launch_bounds__(256, 1)
void flash_attn_kernel(const int* __restrict__ mask)
{
    extern __shared__ float smem[];
    float* Qs  = smem;                 // [128][64] q-row major, pre-scaled
    float* Kts = Qs  + 128 * 64;       // [64][65]  d-major (transposed, padded)
    float* Vs  = Kts + 64 * 65;        // [64][64]  key-row major
    float* Ps  = Vs  + 64 * 64;        // [128][64] probs

    const int t    = threadIdx.x;
    const int tRow = t >> 4, tCol = t & 15;
    const int bh = blockIdx.y;
    const int b  = bh / NH, h = bh % NH;
    const int q0 = blockIdx.x * 128;

    const float* Qg = g_q + ((size_t)bh * SEQ + q0) * DHEAD;
    const float* Kg = g_k + (size_t)bh * SEQ * DHEAD;
    const float* Vg = g_v + (size_t)bh * SEQ * DHEAD;

    // Load Q tile, pre-scaled by 1/sqrt(Dh) = 0.125
    const float scale = 0.125f;
#pragma unroll
    for (int r = 0; r < 8; r++) {
        const int i = t + r * 256;                 // 2048 float4 total
        float4 v = ((const float4*)Qg)[i];
        v.x *= scale; v.y *= scale; v.z *= scale; v.w *= scale;
        ((float4*)Qs)[i] = v;
    }

    float Ot[8][4], mrow[8], lrow[8];
#pragma unroll
    for (int i = 0; i < 8; i++) {
        mrow[i] = -1e30f; lrow[i] = 0.f;
#pragma unroll
        for (int j = 0; j < 4; j++) Ot[i][j] = 0.f;
    }

    __syncthreads();

    for (int kt = 0; kt < SEQ / 64; kt++) {
        // Load K (transposed into d-major, pad 65 => conflict-free) and V
        const float* Kt0 = Kg + (size_t)kt * 64 * DHEAD;
        const float* Vt0 = Vg + (size_t)kt * 64 * DHEAD;
#pragma unroll
        for (int r = 0; r < 4; r++) {
            const int i   = t + r * 256;           // 1024 float4 total
            const int key = i >> 4;
            const int d4  = (i & 15) * 4;
            const float4 kv = ((const float4*)Kt0)[i];
            Kts[(d4 + 0) * 65 + key] = kv.x;
            Kts[(d4 + 1) * 65 + key] = kv.y;
            Kts[(d4 + 2) * 65 + key] = kv.z;
            Kts[(d4 + 3) * 65 + key] = kv.w;
            ((float4*)Vs)[i] = ((const float4*)Vt0)[i];
        }
        __syncthreads();

        // Scores: sc[i][j] = sum_d Qs[row][d] * K[col][d]
        float sc[8][4];
#pragma unroll
        for (int i = 0; i < 8; i++)
#pragma unroll
            for (int j = 0; j < 4; j++) sc[i][j] = 0.f;

#pragma unroll 8
        for (int d = 0; d < DHEAD; d++) {
            float kr[4];
#pragma unroll
            for (int j = 0; j < 4; j++) kr[j] = Kts[d * 65 + tCol * 4 + j];
#pragma unroll
            for (int i = 0; i < 8; i++) {
                const float qv = Qs[(tRow * 8 + i) * 64 + d];
#pragma unroll
                for (int j = 0; j < 4; j++) sc[i][j] += qv * kr[j];
            }
        }

        // Mask + online softmax
        const int kbase = kt * 64;
#pragma unroll
        for (int i = 0; i < 8; i++) {
            const int qrow = q0 + tRow * 8 + i;
            const int4 mv = *(const int4*)(mask +
                ((size_t)b * SEQ + qrow) * SEQ + kbase + tCol * 4);
            if (mv.x == 0) sc[i][0] = -1e9f;
            if (mv.y == 0) sc[i][1] = -1e9f;
            if (mv.z == 0) sc[i][2] = -1e9f;
            if (mv.w == 0) sc[i][3] = -1e9f;

            float mx = fmaxf(fmaxf(sc[i][0], sc[i][1]), fmaxf(sc[i][2], sc[i][3]));
#pragma unroll
            for (int off = 8; off > 0; off >>= 1)
                mx = fmaxf(mx, __shfl_xor_sync(0xffffffffu, mx, off));

            const float mnew = fmaxf(mrow[i], mx);
            const float corr = __expf(mrow[i] - mnew);
            float4 pv;
            pv.x = __expf(sc[i][0] - mnew);
            pv.y = __expf(sc[i][1] - mnew);
            pv.z = __expf(sc[i][2] - mnew);
            pv.w = __expf(sc[i][3] - mnew);
            float ssum = pv.x + pv.y + pv.z + pv.w;
#pragma unroll
            for (int off = 8; off > 0; off >>= 1)
                ssum += __shfl_xor_sync(0xffffffffu, ssum, off);

            lrow[i] = lrow[i] * corr + ssum;
            mrow[i] = mnew;
#pragma unroll
            for (int j = 0; j < 4; j++) Ot[i][j] *= corr;
            *(float4*)(Ps + (tRow * 8 + i) * 64 + tCol * 4) = pv;
        }
        __syncthreads();

        // O += P @ V
#pragma unroll 8
        for (int key = 0; key < 64; key++) {
            float vr[4];
            *(float4*)vr = *(const float4*)(Vs + key * 64 + tCol * 4);
#pragma unroll
            for (int i = 0; i < 8; i++) {
                const float p = Ps[(tRow * 8 + i) * 64 + key];
#pragma unroll
                for (int j = 0; j < 4; j++) Ot[i][j] += p * vr[j];
            }
        }
        __syncthreads();
    }

    // Normalize and write to [B,S,D] scratch (concat heads)
#pragma unroll
    for (int i = 0; i < 8; i++) {
        const int qrow = q0 + tRow * 8 + i;
        const float inv = 1.0f / lrow[i];
        float4 o;
        o.x = Ot[i][0] * inv; o.y = Ot[i][1] * inv;
        o.z = Ot[i][2] * inv; o.w = Ot[i][3] * inv;
        *(float4*)(g_attn + ((size_t)b * SEQ + qrow) * DMODEL + h * DHEAD + tCol * 4) = o;
    }
}

// ---------------------------------------------------------------------------
// Kernel 3: output projection. grid = (N/128, M/128), block = 256.
// ---------------------------------------------------------------------------
__global__ __launch_bounds__(256)
void out_proj_kernel(const float* __restrict__ Wo, const float* __restrict__ bo,
                     float* __restrict__ out)
{
    __shared__ float As[8][128];
    __shared__ float Bs[8][128];

    const int rowBase = blockIdx.y * 128;
    const int colBase = blockIdx.x * 128;

    float acc[8][8];
#pragma unroll
    for (int i = 0; i < 8; i++)
#pragma unroll
        for (int j = 0; j < 8; j++) acc[i][j] = 0.f;

    gemm_mainloop(g_attn + (size_t)rowBase * DMODEL, Wo + colBase, DMODEL, DMODEL,
                  acc, As, Bs);

    const int t = threadIdx.x;
    const int tRow = t >> 4, tCol = t & 15;
#pragma unroll
    for (int i = 0; i < 8; i++) {
        const int r = rowBase + tRow * 8 + i;
#pragma unroll
        for (int j4 = 0; j4 < 8; j4 += 4) {
            const int n = colBase + tCol * 8 + j4;
            float4 o;
            o.x = acc[i][j4 + 0] + bo[n + 0];
            o.y = acc[i][j4 + 1] + bo[n + 1];
            o.z = acc[i][j4 + 2] + bo[n + 2];
            o.w = acc[i][j4 + 3] + bo[n + 3];
            *(float4*)(out + (size_t)r * DMODEL + n) = o;
        }
    }
}

// ---------------------------------------------------------------------------
extern "C" void kernel_launch(void* const* d_in, const int* in_sizes, int n_in,
                              void* d_out, int out_size)
{
    (void)in_sizes; (void)n_in; (void)out_size;
    const float* q_in = (const float*)d_in[0];
    const float* k_in = (const float*)d_in[1];
    const float* v_in = (const float*)d_in[2];
    const int*   mask = (const int*)d_in[3];
    const float* Wq = (const float*)d_in[4];
    const float* bq = (const float*)d_in[5];
    const float* Wk = (const float*)d_in[6];
    const float* bk = (const float*)d_in[7];
    const float* Wv = (const float*)d_in[8];
    const float* bv = (const float*)d_in[9];
    const float* Wo = (const float*)d_in[10];
    const float* bo = (const float*)d_in[11];
    float* out = (float*)d_out;

    // Idempotent, not a stream op — safe under graph capture.
    cudaFuncSetAttribute(flash_attn_kernel,
                         cudaFuncAttributeMaxDynamicSharedMemorySize,
                         ATTN_SMEM_FLOATS * (int)sizeof(float));

    dim3 gP(DMODEL / 128, MTOT / 128, 3);
    qkv_proj_kernel<<<gP, 256>>>(q_in, k_in, v_in, Wq, Wk, Wv, bq, bk, bv);

    dim3 gA(SEQ / 128, NUM_B * NH);
    flash_attn_kernel<<<gA, 256, ATTN_SMEM_FLOATS * sizeof(float)>>>(mask);

    dim3 gO(DMODEL / 128, MTOT / 128);
    out_proj_kernel<<<gO, 256>>>(Wo, bo, out);
}

// round 10
// speedup vs baseline: 4.0981x; 4.0981x over previous
#include <cuda_runtime.h>
#include <cstdint>

#define NUM_B  4
#define SEQ    2048
#define DMODEL 1024
#define NH     16
#define DHEAD  64
#define MTOT   (NUM_B * SEQ)   // 8192

// ---------------------------------------------------------------------------
// Scratch (__device__ globals: allocation-free rule)
// ---------------------------------------------------------------------------
__device__ float g_q   [(size_t)NUM_B * NH * SEQ * DHEAD];   // [bh][s][d]
__device__ float g_k   [(size_t)NUM_B * NH * SEQ * DHEAD];   // [bh][s][d]
__device__ float g_vt  [(size_t)NUM_B * NH * DHEAD * SEQ];   // [bh][d][s]
__device__ float g_attn[(size_t)NUM_B * SEQ * DMODEL];       // [b][s][D]
__device__ float g_wt  [4ull * DMODEL * DMODEL];             // Wt[z][n][k]

// ---------------------------------------------------------------------------
__device__ __forceinline__ float tf32r(float x) {
    uint32_t u;
    asm("cvt.rna.tf32.f32 %0, %1;" : "=r"(u) : "f"(x));
    return __uint_as_float(u);
}

__device__ __forceinline__ void mma_tf32(float c[4], const float a[4], const float b[2]) {
    const uint32_t* A = reinterpret_cast<const uint32_t*>(a);
    const uint32_t* B = reinterpret_cast<const uint32_t*>(b);
    asm volatile(
        "mma.sync.aligned.m16n8k8.row.col.f32.tf32.tf32.f32 "
        "{%0,%1,%2,%3},{%4,%5,%6,%7},{%8,%9},{%0,%1,%2,%3};\n"
        : "+f"(c[0]), "+f"(c[1]), "+f"(c[2]), "+f"(c[3])
        : "r"(A[0]), "r"(A[1]), "r"(A[2]), "r"(A[3]), "r"(B[0]), "r"(B[1]));
}

// ---------------------------------------------------------------------------
// Weight transpose: g_wt[z][n][k] = W_z[k][n].  grid(32,32,4), block(32,8)
// ---------------------------------------------------------------------------
__global__ void transpose_weights(const float* __restrict__ Wq, const float* __restrict__ Wk,
                                  const float* __restrict__ Wv, const float* __restrict__ Wo)
{
    __shared__ float tile[32][33];
    const float* W = (blockIdx.z == 0) ? Wq : (blockIdx.z == 1) ? Wk
                   : (blockIdx.z == 2) ? Wv : Wo;
    float* Wt = g_wt + (size_t)blockIdx.z * DMODEL * DMODEL;
    const int x0 = blockIdx.x * 32, y0 = blockIdx.y * 32;
    const int tx = threadIdx.x, ty = threadIdx.y;
#pragma unroll
    for (int r = 0; r < 32; r += 8)
        tile[ty + r][tx] = W[(size_t)(y0 + ty + r) * DMODEL + x0 + tx];
    __syncthreads();
#pragma unroll
    for (int r = 0; r < 32; r += 8)
        Wt[(size_t)(x0 + ty + r) * DMODEL + y0 + tx] = tile[tx][ty + r];
}

// ---------------------------------------------------------------------------
// tf32 GEMM mainloop: C(128x128) = A[128 x K] * Bt[128 x K]^T, K=1024.
// 256 thr, 8 warps (wM 0..3 x wN 0..1), warp tile 32x64. BK=32, dbl-buffered.
// smem row layout: (idx*2 + g)*24 + p,  p(k16) = (k16%4)*4 + k16/4.
// ---------------------------------------------------------------------------
#define GEMM_SMEM_BYTES (2 * 2 * 256 * 24 * 4)   // 98304

__device__ __forceinline__ void gemm_tc_body(
    const float* __restrict__ Ablk, const float* __restrict__ Btblk,
    float* sm, float (&acc)[2][8][4])
{
    const int t = threadIdx.x, lane = t & 31, wid = t >> 5;
    const int gid = lane >> 2, tig = lane & 3;
    const int wM = wid >> 1, wN = wid & 1;

    float4 ar[4], br[4];
    auto ldg = [&](int k0) {
#pragma unroll
        for (int r = 0; r < 4; r++) {
            const int i = t + r * 256;
            const int m = i >> 3, kq = i & 7;
            ar[r] = *(const float4*)(Ablk  + (size_t)m * DMODEL + k0 + kq * 4);
            br[r] = *(const float4*)(Btblk + (size_t)m * DMODEL + k0 + kq * 4);
        }
    };
    ldg(0);

    for (int k0 = 0; k0 < DMODEL; k0 += 32) {
        float* As = sm + ((k0 >> 5) & 1) * 12288;
        float* Bs = As + 6144;
#pragma unroll
        for (int r = 0; r < 4; r++) {
            const int i = t + r * 256;
            const int m = i >> 3, kq = i & 7;
            const int g = kq >> 2, q = kq & 3;
            float* d = As + (m * 2 + g) * 24 + q;
            d[0]  = tf32r(ar[r].x); d[4]  = tf32r(ar[r].y);
            d[8]  = tf32r(ar[r].z); d[12] = tf32r(ar[r].w);
            float* e = Bs + (m * 2 + g) * 24 + q;
            e[0]  = tf32r(br[r].x); e[4]  = tf32r(br[r].y);
            e[8]  = tf32r(br[r].z); e[12] = tf32r(br[r].w);
        }
        __syncthreads();
        if (k0 + 32 < DMODEL) ldg(k0 + 32);

#pragma unroll
        for (int g = 0; g < 2; g++) {
            float4 alo[2], ahi[2], bf[8];
#pragma unroll
            for (int mi = 0; mi < 2; mi++) {
                const int r0 = wM * 32 + mi * 16 + gid;
                alo[mi] = *(const float4*)(As + (r0 * 2 + g) * 24 + tig * 4);
                ahi[mi] = *(const float4*)(As + ((r0 + 8) * 2 + g) * 24 + tig * 4);
            }
#pragma unroll
            for (int ni = 0; ni < 8; ni++) {
                const int n = wN * 64 + ni * 8 + gid;
                bf[ni] = *(const float4*)(Bs + (n * 2 + g) * 24 + tig * 4);
            }
#pragma unroll
            for (int s = 0; s < 2; s++) {
                float a[2][4];
#pragma unroll
                for (int mi = 0; mi < 2; mi++) {
                    a[mi][0] = s ? alo[mi].z : alo[mi].x;
                    a[mi][1] = s ? ahi[mi].z : ahi[mi].x;
                    a[mi][2] = s ? alo[mi].w : alo[mi].y;
                    a[mi][3] = s ? ahi[mi].w : ahi[mi].y;
                }
#pragma unroll
                for (int ni = 0; ni < 8; ni++) {
                    float b2[2];
                    b2[0] = s ? bf[ni].z : bf[ni].x;
                    b2[1] = s ? bf[ni].w : bf[ni].y;
#pragma unroll
                    for (int mi = 0; mi < 2; mi++)
                        mma_tf32(acc[mi][ni], a[mi], b2);
                }
            }
        }
        __syncthreads();
    }
}

// ---------------------------------------------------------------------------
// Kernel 1: QKV projection. grid(8,64,3), block 256.
// sel 0/1 -> g_q/g_k [bh][s][d]; sel 2 -> g_vt [bh][d][s].
// ---------------------------------------------------------------------------
__global__ __launch_bounds__(256, 1)
void qkv_tc_kernel(const float* __restrict__ xq, const float* __restrict__ xk,
                   const float* __restrict__ xv,
                   const float* __restrict__ bq, const float* __restrict__ bk,
                   const float* __restrict__ bv)
{
    extern __shared__ float sm[];
    const int sel = blockIdx.z;
    const float* X    = (sel == 0) ? xq : (sel == 1) ? xk : xv;
    const float* bias = (sel == 0) ? bq : (sel == 1) ? bk : bv;
    const float* Bt   = g_wt + (size_t)sel * DMODEL * DMODEL;

    const int rowBase = blockIdx.y * 128;
    const int colBase = blockIdx.x * 128;

    float acc[2][8][4];
#pragma unroll
    for (int mi = 0; mi < 2; mi++)
#pragma unroll
        for (int ni = 0; ni < 8; ni++)
#pragma unroll
            for (int e = 0; e < 4; e++) acc[mi][ni][e] = 0.f;

    gemm_tc_body(X + (size_t)rowBase * DMODEL, Bt + (size_t)colBase * DMODEL, sm, acc);

    const int t = threadIdx.x, lane = t & 31, wid = t >> 5;
    const int gid = lane >> 2, tig = lane & 3;
    const int wM = wid >> 1, wN = wid & 1;

#pragma unroll
    for (int mi = 0; mi < 2; mi++)
#pragma unroll
        for (int hh = 0; hh < 2; hh++) {
            const int r = rowBase + wM * 32 + mi * 16 + hh * 8 + gid;
            const int b = r >> 11, s = r & 2047;
#pragma unroll
            for (int ni = 0; ni < 8; ni++) {
                const int n = colBase + wN * 64 + ni * 8 + tig * 2;
                const float v0 = acc[mi][ni][hh * 2 + 0] + bias[n + 0];
                const float v1 = acc[mi][ni][hh * 2 + 1] + bias[n + 1];
                const int h = n >> 6, d = n & 63;
                if (sel == 2) {
                    float* vt = g_vt + (size_t)(b * NH + h) * DHEAD * SEQ;
                    vt[(size_t)d * SEQ + s]       = v0;
                    vt[(size_t)(d + 1) * SEQ + s] = v1;
                } else {
                    float* dst = ((sel == 0) ? g_q : g_k) +
                        ((size_t)(b * NH + h) * SEQ + s) * DHEAD + d;
                    *(float2*)dst = make_float2(v0, v1);
                }
            }
        }
}

// ---------------------------------------------------------------------------
// Kernel 2: flash attention (tf32 mma). grid(16,64), block 256.
// 8 warps; warp tile = 16 q-rows x 64 keys (S) / 16 q-rows x 64 d (O).
// Every row's FULL key range lives in one warp quad -> stats reduce via
// shfl xor 1,2 only (this fixes the R9 cross-warp normalization bug).
// smem floats: Qs 10240 | Ks 2x5120 | Vs 2x5120 | Ps 10240 = 163840 B
// row layout: (idx*4 + g)*20 + p(k16)
// ---------------------------------------------------------------------------
#define ATTN_SMEM_BYTES (40960 * 4)

__global__ __launch_bounds__(256, 1)
void flash_tc_kernel(const int* __restrict__ mask)
{
    extern __shared__ float sm[];
    float* Qs = sm;
    float* Ks = sm + 10240;
    float* Vs = sm + 20480;
    float* Ps = sm + 30720;

    const int t = threadIdx.x, lane = t & 31, wid = t >> 5;   // wid 0..7
    const int gid = lane >> 2, tig = lane & 3;

    const int bh = blockIdx.y;
    const int b = bh >> 4, h = bh & 15;
    const int q0 = blockIdx.x * 128;

    const float* Qg = g_q  + ((size_t)bh * SEQ + q0) * DHEAD;
    const float* Kg = g_k  + (size_t)bh * SEQ * DHEAD;
    const float* Vt = g_vt + (size_t)bh * DHEAD * SEQ;

    // stage Q (x 1/sqrt(64)), tf32
#pragma unroll
    for (int r = 0; r < 8; r++) {
        const int i = t + r * 256;
        const int m = i >> 4, c = i & 15;
        float4 v = *(const float4*)(Qg + (size_t)m * DHEAD + c * 4);
        float* d = Qs + (m * 4 + (c >> 2)) * 20 + (c & 3);
        d[0]  = tf32r(v.x * 0.125f);
        d[4]  = tf32r(v.y * 0.125f);
        d[8]  = tf32r(v.z * 0.125f);
        d[12] = tf32r(v.w * 0.125f);
    }

    float Ot[8][4], mrow[2], lrow[2];
#pragma unroll
    for (int nd = 0; nd < 8; nd++)
#pragma unroll
        for (int e = 0; e < 4; e++) Ot[nd][e] = 0.f;
    mrow[0] = mrow[1] = -1e30f;
    lrow[0] = lrow[1] = 0.f;

    float4 kr[4], vr[4];
    auto preloadKV = [&](int kt) {
        const int kb2 = kt * 64;
#pragma unroll
        for (int r = 0; r < 4; r++) {
            const int i = t + r * 256;
            const int a = i >> 4, c = i & 15;
            kr[r] = *(const float4*)(Kg + (size_t)(kb2 + a) * DHEAD + c * 4);
            vr[r] = *(const float4*)(Vt + (size_t)a * SEQ + kb2 + c * 4);
        }
    };
    preloadKV(0);

    for (int kt = 0; kt < SEQ / 64; kt++) {
        float* Kb = Ks + (kt & 1) * 5120;
        float* Vb = Vs + (kt & 1) * 5120;
#pragma unroll
        for (int r = 0; r < 4; r++) {
            const int i = t + r * 256;
            const int a = i >> 4, c = i & 15;
            float* dk = Kb + (a * 4 + (c >> 2)) * 20 + (c & 3);
            dk[0]  = tf32r(kr[r].x); dk[4]  = tf32r(kr[r].y);
            dk[8]  = tf32r(kr[r].z); dk[12] = tf32r(kr[r].w);
            float* dv = Vb + (a * 4 + (c >> 2)) * 20 + (c & 3);
            dv[0]  = tf32r(vr[r].x); dv[4]  = tf32r(vr[r].y);
            dv[8]  = tf32r(vr[r].z); dv[12] = tf32r(vr[r].w);
        }
        __syncthreads();
        if (kt + 1 < SEQ / 64) preloadKV(kt + 1);

        // ---- S = Q K^T : warp tile 16 rows x 64 keys ----
        float Sc[8][4];
#pragma unroll
        for (int ni = 0; ni < 8; ni++)
#pragma unroll
            for (int e = 0; e < 4; e++) Sc[ni][e] = 0.f;

#pragma unroll
        for (int g = 0; g < 4; g++) {
            const int r0 = wid * 16 + gid;
            float4 alo = *(const float4*)(Qs + (r0 * 4 + g) * 20 + tig * 4);
            float4 ahi = *(const float4*)(Qs + ((r0 + 8) * 4 + g) * 20 + tig * 4);
            float4 bf[8];
#pragma unroll
            for (int ni = 0; ni < 8; ni++) {
                const int n = ni * 8 + gid;
                bf[ni] = *(const float4*)(Kb + (n * 4 + g) * 20 + tig * 4);
            }
#pragma unroll
            for (int s = 0; s < 2; s++) {
                float a[4];
                a[0] = s ? alo.z : alo.x;
                a[1] = s ? ahi.z : ahi.x;
                a[2] = s ? alo.w : alo.y;
                a[3] = s ? ahi.w : ahi.y;
#pragma unroll
                for (int ni = 0; ni < 8; ni++) {
                    float b2[2];
                    b2[0] = s ? bf[ni].z : bf[ni].x;
                    b2[1] = s ? bf[ni].w : bf[ni].y;
                    mma_tf32(Sc[ni], a, b2);
                }
            }
        }

        // ---- mask + online softmax (full 64-key row inside this quad) ----
        const int kb = kt * 64;
#pragma unroll
        for (int hh = 0; hh < 2; hh++) {
            const int rloc = wid * 16 + hh * 8 + gid;
            const int grow = q0 + rloc;
            const int* mp = mask + ((size_t)b * SEQ + grow) * SEQ + kb;
            float sv[8][2];
            float mx = -1e30f;
#pragma unroll
            for (int ni = 0; ni < 8; ni++) {
                const int2 mv = *(const int2*)(mp + ni * 8 + tig * 2);
                const float s0 = (mv.x == 0) ? -1e9f : Sc[ni][hh * 2 + 0];
                const float s1 = (mv.y == 0) ? -1e9f : Sc[ni][hh * 2 + 1];
                sv[ni][0] = s0; sv[ni][1] = s1;
                mx = fmaxf(mx, fmaxf(s0, s1));
            }
            mx = fmaxf(mx, __shfl_xor_sync(0xffffffffu, mx, 1));
            mx = fmaxf(mx, __shfl_xor_sync(0xffffffffu, mx, 2));

            const float mold = mrow[hh];
            const float mnew = fmaxf(mold, mx);
            const float corr = __expf(mold - mnew);
            float sum = 0.f;
#pragma unroll
            for (int ni = 0; ni < 8; ni++) {
                const float p0 = __expf(sv[ni][0] - mnew);
                const float p1 = __expf(sv[ni][1] - mnew);
                sum += p0 + p1;
                const int c0 = ni * 8 + tig * 2;       // 0..63 (even)
                const int g = c0 >> 4;
                const int k16 = c0 & 15;
                Ps[(rloc * 4 + g) * 20 + (k16 & 3) * 4 + (k16 >> 2)]             = tf32r(p0);
                Ps[(rloc * 4 + g) * 20 + ((k16 + 1) & 3) * 4 + ((k16 + 1) >> 2)] = tf32r(p1);
            }
            sum += __shfl_xor_sync(0xffffffffu, sum, 1);
            sum += __shfl_xor_sync(0xffffffffu, sum, 2);
            lrow[hh] = lrow[hh] * corr + sum;
            mrow[hh] = mnew;
#pragma unroll
            for (int nd = 0; nd < 8; nd++) {
                Ot[nd][hh * 2 + 0] *= corr;
                Ot[nd][hh * 2 + 1] *= corr;
            }
        }
        __syncwarp();   // Ps written by this warp's lanes, read cross-lane below

        // ---- O += P V : warp tile 16 rows x 64 d ----
#pragma unroll
        for (int g = 0; g < 4; g++) {
            const int r0 = wid * 16 + gid;
            float4 plo = *(const float4*)(Ps + (r0 * 4 + g) * 20 + tig * 4);
            float4 phi = *(const float4*)(Ps + ((r0 + 8) * 4 + g) * 20 + tig * 4);
            float4 bf[8];
#pragma unroll
            for (int nd = 0; nd < 8; nd++) {
                const int n = nd * 8 + gid;
                bf[nd] = *(const float4*)(Vb + (n * 4 + g) * 20 + tig * 4);
            }
#pragma unroll
            for (int s = 0; s < 2; s++) {
                float a[4];
                a[0] = s ? plo.z : plo.x;
                a[1] = s ? phi.z : phi.x;
                a[2] = s ? plo.w : plo.y;
                a[3] = s ? phi.w : phi.y;
#pragma unroll
                for (int nd = 0; nd < 8; nd++) {
                    float b2[2];
                    b2[0] = s ? bf[nd].z : bf[nd].x;
                    b2[1] = s ? bf[nd].w : bf[nd].y;
                    mma_tf32(Ot[nd], a, b2);
                }
            }
        }
        // next-iteration __syncthreads (after staging) orders Ps/Vb reuse
    }

    // ---- normalize + write [b][s][h*64+d] ----
#pragma unroll
    for (int hh = 0; hh < 2; hh++) {
        const int rloc = wid * 16 + hh * 8 + gid;
        const int grow = q0 + rloc;
        const float inv = 1.0f / lrow[hh];
        float* op = g_attn + ((size_t)b * SEQ + grow) * DMODEL + h * DHEAD;
#pragma unroll
        for (int nd = 0; nd < 8; nd++) {
            const int d = nd * 8 + tig * 2;
            *(float2*)(op + d) = make_float2(Ot[nd][hh * 2 + 0] * inv,
                                             Ot[nd][hh * 2 + 1] * inv);
        }
    }
}

// ---------------------------------------------------------------------------
// Kernel 3: output projection. grid(8,64), block 256.
// ---------------------------------------------------------------------------
__global__ __launch_bounds__(256, 1)
void out_tc_kernel(const float* __restrict__ bo, float* __restrict__ out)
{
    extern __shared__ float sm[];
    const float* Bt = g_wt + 3ull * DMODEL * DMODEL;
    const int rowBase = blockIdx.y * 128;
    const int colBase = blockIdx.x * 128;

    float acc[2][8][4];
#pragma unroll
    for (int mi = 0; mi < 2; mi++)
#pragma unroll
        for (int ni = 0; ni < 8; ni++)
#pragma unroll
            for (int e = 0; e < 4; e++) acc[mi][ni][e] = 0.f;

    gemm_tc_body(g_attn + (size_t)rowBase * DMODEL, Bt + (size_t)colBase * DMODEL, sm, acc);

    const int t = threadIdx.x, lane = t & 31, wid = t >> 5;
    const int gid = lane >> 2, tig = lane & 3;
    const int wM = wid >> 1, wN = wid & 1;

#pragma unroll
    for (int mi = 0; mi < 2; mi++)
#pragma unroll
        for (int hh = 0; hh < 2; hh++) {
            const int r = rowBase + wM * 32 + mi * 16 + hh * 8 + gid;
#pragma unroll
            for (int ni = 0; ni < 8; ni++) {
                const int n = colBase + wN * 64 + ni * 8 + tig * 2;
                *(float2*)(out + (size_t)r * DMODEL + n) =
                    make_float2(acc[mi][ni][hh * 2 + 0] + bo[n + 0],
                                acc[mi][ni][hh * 2 + 1] + bo[n + 1]);
            }
        }
}

// ---------------------------------------------------------------------------
extern "C" void kernel_launch(void* const* d_in, const int* in_sizes, int n_in,
                              void* d_out, int out_size)
{
    (void)in_sizes; (void)n_in; (void)out_size;
    const float* q_in = (const float*)d_in[0];
    const float* k_in = (const float*)d_in[1];
    const float* v_in = (const float*)d_in[2];
    const int*   mask = (const int*)d_in[3];
    const float* Wq = (const float*)d_in[4];
    const float* bq = (const float*)d_in[5];
    const float* Wk = (const float*)d_in[6];
    const float* bk = (const float*)d_in[7];
    const float* Wv = (const float*)d_in[8];
    const float* bv = (const float*)d_in[9];
    const float* Wo = (const float*)d_in[10];
    const float* bo = (const float*)d_in[11];
    float* out = (float*)d_out;

    cudaFuncSetAttribute(qkv_tc_kernel,
        cudaFuncAttributeMaxDynamicSharedMemorySize, GEMM_SMEM_BYTES);
    cudaFuncSetAttribute(out_tc_kernel,
        cudaFuncAttributeMaxDynamicSharedMemorySize, GEMM_SMEM_BYTES);
    cudaFuncSetAttribute(flash_tc_kernel,
        cudaFuncAttributeMaxDynamicSharedMemorySize, ATTN_SMEM_BYTES);

    transpose_weights<<<dim3(32, 32, 4), dim3(32, 8)>>>(Wq, Wk, Wv, Wo);

    dim3 gP(DMODEL / 128, MTOT / 128, 3);
    qkv_tc_kernel<<<gP, 256, GEMM_SMEM_BYTES>>>(q_in, k_in, v_in, bq, bk, bv);

    dim3 gA(SEQ / 128, NUM_B * NH);
    flash_tc_kernel<<<gA, 256, ATTN_SMEM_BYTES>>>(mask);

    dim3 gO(DMODEL / 128, MTOT / 128);
    out_tc_kernel<<<gO, 256, GEMM_SMEM_BYTES>>>(bo, out);
}